// round 16
// baseline (speedup 1.0000x reference)
#include <cuda_runtime.h>

// PositionBias: out[b,i0,i1,n] = x[b,i0,i1,n] + bias[min(|s_b - i0 + i1|, 127), n]
//   x: [8,256,256,64] f32 (134 MB), crop_x/crop_y: [8,2] i32, bias: [128,64] f32 (32 KB)
// R5: UNROLL4 multi-wave 46.4us DRAM 74.9% | R6: UNROLL8 multi-wave 43.5us DRAM 72.7%.
// R11: single-wave persistent grid, GRID = 4*152 = 608 (GB300 has 152 SMs) so every
// SM hosts exactly 4 resident CTAs. Each CTA grid-strides over ~7 tiles; the DRAM
// queue never drains at wave boundaries. Inner tile identical to R6.

#define B_DIM 8
#define C_DIM 256               // Cx == Cy == 256
#define NBINS 64
#define F4_PER_POS (NBINS / 4)  // 16 float4 per (b,i0,i1)
#define IDX_CLAMP 127           // bias_size - 1
#define UNROLL 8
#define THREADS 256

#define TILE_F4      (UNROLL * THREADS)                          // 2048 float4 = 128 positions
#define TOTAL_F4     ((B_DIM * C_DIM * C_DIM * NBINS) / 4)       // 8,388,608
#define TILES_TOTAL  (TOTAL_F4 / TILE_F4)                        // 4096
#define GRID         (4 * 152)                                   // 608: one wave, 4 CTAs/SM exact on GB300

__device__ __forceinline__ float4 f4add(float4 a, float4 b) {
    float4 o; o.x = a.x + b.x; o.y = a.y + b.y; o.z = a.z + b.z; o.w = a.w + b.w;
    return o;
}

__global__ void __launch_bounds__(THREADS)
position_bias_kernel(const float4* __restrict__ x,
                     const int*    __restrict__ crop_x,
                     const int*    __restrict__ crop_y,
                     const float4* __restrict__ bias,
                     float4*       __restrict__ out)
{
#pragma unroll 1
    for (unsigned tile = blockIdx.x; tile < TILES_TOTAL; tile += GRID) {
        // Tile = 128 positions: never crosses an i0 (128 | 256) or batch boundary,
        // so b, i0, s are tile-uniform.
        unsigned posbase = tile * (TILE_F4 / F4_PER_POS);        // tile * 128
        unsigned i0 = (posbase >> 8) & (C_DIM - 1);
        unsigned bb = posbase >> 16;
        int s  = __ldg(&crop_x[2 * bb]) - __ldg(&crop_y[2 * bb]);
        int s0 = s - (int)i0;                                    // d = s0 + i1

        unsigned base = tile * TILE_F4 + threadIdx.x;

        // Front-batched independent streaming loads (coalesced, MLP = 8).
        float4 xv[UNROLL];
#pragma unroll
        for (int u = 0; u < UNROLL; u++)
            xv[u] = __ldcs(&x[base + u * THREADS]);

#pragma unroll
        for (int u = 0; u < UNROLL; u++) {
            unsigned g  = base + u * THREADS;
            unsigned f  = g & (F4_PER_POS - 1);
            unsigned i1 = (g >> 4) & (C_DIM - 1);
            int idx = min(abs(s0 + (int)i1), IDX_CLAMP);
            float4 bv = __ldg(&bias[idx * F4_PER_POS + f]);
            __stcs(&out[g], f4add(xv[u], bv));
        }
    }
}

extern "C" void kernel_launch(void* const* d_in, const int* in_sizes, int n_in,
                              void* d_out, int out_size)
{
    const float4* x      = (const float4*)d_in[0];
    const int*    crop_x = (const int*)d_in[1];
    const int*    crop_y = (const int*)d_in[2];
    const float4* bias   = (const float4*)d_in[3];
    float4*       out    = (float4*)d_out;

    position_bias_kernel<<<GRID, THREADS>>>(x, crop_x, crop_y, bias, out);
}